// round 13
// baseline (speedup 1.0000x reference)
#include <cuda_runtime.h>
#include <cuda_fp16.h>
#include <cstdint>

// Problem constants
#define BB   2
#define SS   2048
#define EE   1024
#define HH   16
#define HKV  4
#define DD   64
#define KVE  (HKV * DD)   // 256
#define MM   (BB * SS)    // 4096

// Scratch (allocation-free rule: __device__ globals) — all fp16
__device__ __half g_Qh[(size_t)MM * EE];    // Q (pre-scaled by 0.125*log2e)
__device__ __half g_Kh[(size_t)MM * KVE];   // K
__device__ __half g_Vth[(size_t)KVE * MM];  // V transposed [d][pos]
__device__ __half g_Ch[(size_t)MM * EE];    // context
__device__ __half g_xh[(size_t)MM * EE];    // x
__device__ __half g_wqh[(size_t)EE * EE];
__device__ __half g_wkh[(size_t)KVE * EE];
__device__ __half g_wvh[(size_t)KVE * EE];
__device__ __half g_woh[(size_t)EE * EE];

__device__ __forceinline__ void mma_f16(float* c, const uint32_t* a,
                                        uint32_t b0, uint32_t b1) {
    asm volatile(
        "mma.sync.aligned.m16n8k16.row.col.f32.f16.f16.f32 "
        "{%0,%1,%2,%3}, {%4,%5,%6,%7}, {%8,%9}, {%0,%1,%2,%3};"
        : "+f"(c[0]), "+f"(c[1]), "+f"(c[2]), "+f"(c[3])
        : "r"(a[0]), "r"(a[1]), "r"(a[2]), "r"(a[3]), "r"(b0), "r"(b1));
}
__device__ __forceinline__ void ldsm_x4(uint32_t* r, uint32_t addr) {
    asm volatile("ldmatrix.sync.aligned.m8n8.x4.shared.b16 {%0,%1,%2,%3}, [%4];"
                 : "=r"(r[0]), "=r"(r[1]), "=r"(r[2]), "=r"(r[3])
                 : "r"(addr));
}
__device__ __forceinline__ void cp16(uint32_t d, const void* s) {
    asm volatile("cp.async.cg.shared.global [%0], [%1], 16;"
                 :: "r"(d), "l"(s) : "memory");
}
__device__ __forceinline__ void cp_commit() {
    asm volatile("cp.async.commit_group;" ::: "memory");
}
__device__ __forceinline__ void cp_wait0() {
    asm volatile("cp.async.wait_group 0;" ::: "memory");
}
__device__ __forceinline__ void cp_wait1() {
    asm volatile("cp.async.wait_group 1;" ::: "memory");
}
__device__ __forceinline__ uint32_t cvta_s(const void* p) {
    return (uint32_t)__cvta_generic_to_shared(p);
}
__device__ __forceinline__ uint32_t pack_h2(float lo, float hi) {
    __half2 h = __floats2half2_rn(lo, hi);
    return *(uint32_t*)&h;
}
__device__ __forceinline__ float ex2f(float x) {
    float y;
    asm("ex2.approx.f32 %0, %1;" : "=f"(y) : "f"(x));
    return y;
}

// Q projection scale: 1/sqrt(64) * log2(e)  (softmax done in base-2)
#define QSCALE 0.1803368801111244f

// ===========================================================================
// Prep: convert x + all weights to fp16
// ===========================================================================
#define NX  (MM * EE)
#define NWQ (EE * EE)
#define NWK (KVE * EE)
#define NTOT (NX + NWQ + 2 * NWK + NWQ)

__global__ void __launch_bounds__(256)
prep_h(const float* __restrict__ x,
       const float* __restrict__ wq, const float* __restrict__ wk,
       const float* __restrict__ wv, const float* __restrict__ wo)
{
    const int nvec = NTOT / 8;
    for (int i = blockIdx.x * blockDim.x + threadIdx.x; i < nvec;
         i += gridDim.x * blockDim.x) {
        const int e = i * 8;
        const float* src;
        __half* dst;
        int off;
        if (e < NX)                    { src = x;  dst = g_xh;  off = e; }
        else if (e < NX + NWQ)         { src = wq; dst = g_wqh; off = e - NX; }
        else if (e < NX + NWQ + NWK)   { src = wk; dst = g_wkh; off = e - NX - NWQ; }
        else if (e < NX + NWQ + 2*NWK) { src = wv; dst = g_wvh; off = e - NX - NWQ - NWK; }
        else                           { src = wo; dst = g_woh; off = e - NX - NWQ - 2*NWK; }
        float4 v0 = *(const float4*)(src + off);
        float4 v1 = *(const float4*)(src + off + 4);
        __half2 h[4];
        h[0] = __floats2half2_rn(v0.x, v0.y);
        h[1] = __floats2half2_rn(v0.z, v0.w);
        h[2] = __floats2half2_rn(v1.x, v1.y);
        h[3] = __floats2half2_rn(v1.z, v1.w);
        *(uint4*)(dst + off) = *(uint4*)h;
    }
}

// ===========================================================================
// fp16 tensor-core GEMM core (m16n8k16): 128x128 CTA tile, 256 thr,
// 8 warps (2M x 4N), warp 64x32. BK=64 halves, 3-stage cp.async ring.
// OUT: 0 = fp32, 1 = fp16, 2 = fp16 transposed, 3 = fp16 * QSCALE (Q)
// (round-11 config, passing @ 227us — unchanged except QSCALE)
// ===========================================================================
#define GBK   64
#define GROW  144
#define GBUFB (128 * GROW)
#define GSTG  3
#define GSMEM (2 * GSTG * GBUFB)       // 110592 bytes

template <int OUT>
__device__ __forceinline__ void gemm_core(
    const __half* __restrict__ A, const __half* __restrict__ W,
    const float* __restrict__ bias, void* __restrict__ Cv,
    int Nc, int row0)
{
    extern __shared__ char smraw[];
    const uint32_t sbase = cvta_s(smraw);

    const int tid = threadIdx.x;

    const int r   = tid >> 1;
    const int seg = (tid & 1) * 32;
    const __half* Ag = A + (size_t)(row0 + r) * EE + seg;
    const __half* Wg = W + (size_t)r * EE + seg;
    const uint32_t Asd = sbase + r * GROW + seg * 2;
    const uint32_t Bsd = sbase + GSTG * GBUFB + r * GROW + seg * 2;

    const int lane = tid & 31;
    const int wid  = tid >> 5;
    const int wm   = (wid & 1) * 64;
    const int wn   = (wid >> 1) * 32;
    const int g    = lane >> 2;
    const int tig  = lane & 3;

    const uint32_t aoff = (wm + (lane & 15)) * GROW + ((lane & 16) ? 16 : 0);
    const uint32_t boff = (wn + (lane & 15)) * GROW + ((lane & 16) ? 16 : 0);

    float acc[4][4][4];
#pragma unroll
    for (int mt = 0; mt < 4; mt++)
#pragma unroll
        for (int nt = 0; nt < 4; nt++)
#pragma unroll
            for (int i = 0; i < 4; i++) acc[mt][nt][i] = 0.f;

#pragma unroll
    for (int s = 0; s < 2; s++) {
#pragma unroll
        for (int i = 0; i < 4; i++) {
            cp16(Asd + s * GBUFB + i * 16, Ag + s * GBK + i * 8);
            cp16(Bsd + s * GBUFB + i * 16, Wg + s * GBK + i * 8);
        }
        cp_commit();
    }

    const int NI = EE / GBK;
    int bcur = 0, bpre = 2;
    for (int it = 0; it < NI; it++) {
        if (it + 1 < NI) cp_wait1(); else cp_wait0();
        __syncthreads();

        if (it + 2 < NI) {
            const __half* a = Ag + (it + 2) * GBK;
            const __half* w = Wg + (it + 2) * GBK;
            const uint32_t ad = Asd + bpre * GBUFB;
            const uint32_t bd = Bsd + bpre * GBUFB;
#pragma unroll
            for (int i = 0; i < 4; i++) {
                cp16(ad + i * 16, a + i * 8);
                cp16(bd + i * 16, w + i * 8);
            }
            cp_commit();
        }

        const uint32_t Ab = sbase + bcur * GBUFB + aoff;
        const uint32_t Bb = sbase + GSTG * GBUFB + bcur * GBUFB + boff;
#pragma unroll
        for (int ks = 0; ks < 4; ks++) {
            uint32_t a[4][4], b[2][4];
#pragma unroll
            for (int mt = 0; mt < 4; mt++)
                ldsm_x4(a[mt], Ab + mt * 16 * GROW + ks * 32);
#pragma unroll
            for (int np = 0; np < 2; np++)
                ldsm_x4(b[np], Bb + np * 16 * GROW + ks * 32);
#pragma unroll
            for (int mt = 0; mt < 4; mt++)
#pragma unroll
                for (int np = 0; np < 2; np++) {
                    mma_f16(acc[mt][2*np],   a[mt], b[np][0], b[np][2]);
                    mma_f16(acc[mt][2*np+1], a[mt], b[np][1], b[np][3]);
                }
        }

        bcur = (bcur + 1 == GSTG) ? 0 : bcur + 1;
        bpre = (bpre + 1 == GSTG) ? 0 : bpre + 1;
    }

#pragma unroll
    for (int mt = 0; mt < 4; mt++) {
        const int rowa = row0 + wm + mt * 16 + g;
#pragma unroll
        for (int nt = 0; nt < 4; nt++) {
            const int cola = wn + nt * 8 + 2 * tig;
            const float2 bv = *(const float2*)(bias + cola);
            float s0 = acc[mt][nt][0] + bv.x;
            float s1 = acc[mt][nt][1] + bv.y;
            float s2 = acc[mt][nt][2] + bv.x;
            float s3 = acc[mt][nt][3] + bv.y;
            if (OUT == 0) {
                float* C = (float*)Cv;
                *(float2*)(C + (size_t)rowa * Nc + cola)       = make_float2(s0, s1);
                *(float2*)(C + (size_t)(rowa + 8) * Nc + cola) = make_float2(s2, s3);
            } else if (OUT == 2) {
                __half* C = (__half*)Cv;
                C[(size_t)cola * MM + rowa]           = __float2half_rn(s0);
                C[(size_t)(cola + 1) * MM + rowa]     = __float2half_rn(s1);
                C[(size_t)cola * MM + rowa + 8]       = __float2half_rn(s2);
                C[(size_t)(cola + 1) * MM + rowa + 8] = __float2half_rn(s3);
            } else {
                const float sc = (OUT == 3) ? QSCALE : 1.f;
                __half* C = (__half*)Cv;
                __half2 v0 = __floats2half2_rn(s0 * sc, s1 * sc);
                __half2 v1 = __floats2half2_rn(s2 * sc, s3 * sc);
                *(__half2*)(C + (size_t)rowa * Nc + cola)       = v0;
                *(__half2*)(C + (size_t)(rowa + 8) * Nc + cola) = v1;
            }
        }
    }
}

__global__ void __launch_bounds__(256, 2)
gemm_qkv(const float* __restrict__ bq, const float* __restrict__ bk,
         const float* __restrict__ bv)
{
    const int bx   = blockIdx.x;
    const int row0 = blockIdx.y * 128;
    if (bx < 8) {
        const int c0 = bx * 128;
        gemm_core<3>(g_xh, g_wqh + (size_t)c0 * EE, bq + c0, g_Qh + c0, EE, row0);
    } else if (bx < 10) {
        const int c0 = (bx - 8) * 128;
        gemm_core<1>(g_xh, g_wkh + (size_t)c0 * EE, bk + c0, g_Kh + c0, KVE, row0);
    } else {
        const int c0 = (bx - 10) * 128;
        gemm_core<2>(g_xh, g_wvh + (size_t)c0 * EE, bv + c0,
                     g_Vth + (size_t)c0 * MM, KVE, row0);
    }
}

__global__ void __launch_bounds__(256, 2)
gemm_single(const float* __restrict__ bias, float* __restrict__ C)
{
    const int c0 = blockIdx.x * 128;
    gemm_core<0>(g_Ch, g_woh + (size_t)c0 * EE, bias + c0, C + c0, EE,
                 blockIdx.y * 128);
}

// ===========================================================================
// fp16 flash attention: 64 q-rows per CTA, 128 threads (4 warps x 16 rows),
// 4 CTAs/SM. 64-wide KV tiles (round-11 design), 2-stage cp.async ring,
// one barrier per tile. Softmax in base-2 (Q pre-scaled by log2e/8).
// ===========================================================================
#define FROW  144                     // row stride bytes (64 halves + pad)
#define FQB   (64 * FROW)             // 9216
#define FKB   (64 * FROW)             // 9216
#define FSMEM (FQB + 4 * FKB)         // 46080 bytes

__global__ void __launch_bounds__(128, 4)
flash_tc(float* __restrict__ dummy)
{
    extern __shared__ char smraw[];
    const uint32_t sbase = cvta_s(smraw);

    const int tid  = threadIdx.x;
    const int lane = tid & 31;
    const int wid  = tid >> 5;        // 0..3
    const int g    = lane >> 2;
    const int tig  = lane & 3;
    const int m0   = (gridDim.x - 1 - blockIdx.x) * 64;    // heavy-first
    const int h    = blockIdx.y;
    const int b    = blockIdx.z;
    const int kvh  = h >> 2;

    // K/V staging: 2 threads per row (64 rows), 32 halves (64 B = 4 cp16) each
    const int sr  = tid >> 1;         // 0..63
    const int sck = (tid & 1) * 32;
    const __half* kgb = g_Kh + ((size_t)(b * SS + sr)) * KVE + kvh * DD + sck;
    const __half* vgb = g_Vth + ((size_t)(kvh * DD + sr)) * MM + b * SS + sck;
    const uint32_t kd0 = sbase + FQB + sr * FROW + sck * 2;
    const uint32_t vd0 = sbase + FQB + 2 * FKB + sr * FROW + sck * 2;

    // fragment lane offsets
    const uint32_t qoff  = (wid * 16 + (lane & 15)) * FROW + ((lane & 16) ? 16 : 0);
    const uint32_t kvoff = (lane & 15) * FROW + ((lane & 16) ? 16 : 0);

    // stage Q (pre-scaled fp16): 2 threads/row (64 rows), 4 cp16 each
    {
        const int rq   = tid >> 1;
        const int segq = (tid & 1) * 32;
        const __half* qg = g_Qh + ((size_t)(b * SS + m0 + rq)) * EE + h * DD + segq;
        const uint32_t qd = sbase + rq * FROW + segq * 2;
#pragma unroll
        for (int i = 0; i < 4; i++) cp16(qd + i * 16, qg + i * 8);
    }
    // stage KV tile 0 into buffer 0
#pragma unroll
    for (int i = 0; i < 4; i++) {
        cp16(kd0 + i * 16, kgb + i * 8);
        cp16(vd0 + i * 16, vgb + i * 8);
    }
    cp_commit();
    cp_wait0();
    __syncthreads();

    // Q A-fragments (4 k16-steps over d=64)
    uint32_t qa[4][4];
#pragma unroll
    for (int ks = 0; ks < 4; ks++)
        ldsm_x4(qa[ks], sbase + qoff + ks * 32);

    float oacc[8][4];
#pragma unroll
    for (int nt = 0; nt < 8; nt++)
#pragma unroll
        for (int i = 0; i < 4; i++) oacc[nt][i] = 0.f;
    float mrow[2] = { -1e30f, -1e30f };
    float lrow[2] = { 0.f, 0.f };

    const int r0 = m0 + wid * 16 + g;
    const int ntile = m0 / 64 + 1;

    for (int t = 0; t < ntile; t++) {
        const int cb = t & 1;

        if (t > 0) {
            cp_wait0();
            __syncthreads();
        }

        if (t + 1 < ntile) {
            const __half* kg = kgb + (size_t)((t + 1) * 64) * KVE;
            const __half* vg = vgb + (t + 1) * 64;
            const uint32_t kd = kd0 + (1 - cb) * FKB;
            const uint32_t vd = vd0 + (1 - cb) * FKB;
#pragma unroll
            for (int i = 0; i < 4; i++) {
                cp16(kd + i * 16, kg + i * 8);
                cp16(vd + i * 16, vg + i * 8);
            }
            cp_commit();
        }

        const int j0 = t * 64;
        const bool active = (j0 <= m0 + wid * 16 + 15);    // warp-uniform
        if (active) {
            const uint32_t Kc = sbase + FQB + cb * FKB + kvoff;
            const uint32_t Vc = sbase + FQB + 2 * FKB + cb * FKB + kvoff;

            // S' = Q' @ K^T  (already in log2 domain)
            float sc[8][4];
#pragma unroll
            for (int nt = 0; nt < 8; nt++)
#pragma unroll
                for (int i = 0; i < 4; i++) sc[nt][i] = 0.f;
#pragma unroll
            for (int ks = 0; ks < 4; ks++) {
#pragma unroll
                for (int np = 0; np < 4; np++) {
                    uint32_t kb[4];
                    ldsm_x4(kb, Kc + np * 16 * FROW + ks * 32);
                    mma_f16(sc[2*np],   qa[ks], kb[0], kb[2]);
                    mma_f16(sc[2*np+1], qa[ks], kb[1], kb[3]);
                }
            }

            // causal mask (diagonal tiles only)
            if (j0 + 63 > r0) {
#pragma unroll
                for (int nt = 0; nt < 8; nt++) {
                    const int c = j0 + nt * 8 + 2 * tig;
                    if (c     > r0)     sc[nt][0] = -1e30f;
                    if (c + 1 > r0)     sc[nt][1] = -1e30f;
                    if (c     > r0 + 8) sc[nt][2] = -1e30f;
                    if (c + 1 > r0 + 8) sc[nt][3] = -1e30f;
                }
            }

            // row max (quad reduce)
            float tm0 = -1e30f, tm1 = -1e30f;
#pragma unroll
            for (int nt = 0; nt < 8; nt++) {
                tm0 = fmaxf(tm0, fmaxf(sc[nt][0], sc[nt][1]));
                tm1 = fmaxf(tm1, fmaxf(sc[nt][2], sc[nt][3]));
            }
            tm0 = fmaxf(tm0, __shfl_xor_sync(0xffffffffu, tm0, 1));
            tm0 = fmaxf(tm0, __shfl_xor_sync(0xffffffffu, tm0, 2));
            tm1 = fmaxf(tm1, __shfl_xor_sync(0xffffffffu, tm1, 1));
            tm1 = fmaxf(tm1, __shfl_xor_sync(0xffffffffu, tm1, 2));

            const float mn0 = fmaxf(mrow[0], tm0);
            const float mn1 = fmaxf(mrow[1], tm1);
            const float cr0 = ex2f(mrow[0] - mn0);
            const float cr1 = ex2f(mrow[1] - mn1);
            mrow[0] = mn0; mrow[1] = mn1;

            float ls0 = 0.f, ls1 = 0.f;
#pragma unroll
            for (int nt = 0; nt < 8; nt++) {
                sc[nt][0] = ex2f(sc[nt][0] - mn0); ls0 += sc[nt][0];
                sc[nt][1] = ex2f(sc[nt][1] - mn0); ls0 += sc[nt][1];
                sc[nt][2] = ex2f(sc[nt][2] - mn1); ls1 += sc[nt][2];
                sc[nt][3] = ex2f(sc[nt][3] - mn1); ls1 += sc[nt][3];
            }
            lrow[0] = lrow[0] * cr0 + ls0;
            lrow[1] = lrow[1] * cr1 + ls1;
#pragma unroll
            for (int nt = 0; nt < 8; nt++) {
                oacc[nt][0] *= cr0; oacc[nt][1] *= cr0;
                oacc[nt][2] *= cr1; oacc[nt][3] *= cr1;
            }

            // O += P @ V — P converted in-register (C-frag == A-frag for f16)
#pragma unroll
            for (int ks = 0; ks < 4; ks++) {   // kv chunks of 16
                uint32_t pa[4];
                pa[0] = pack_h2(sc[2*ks][0],   sc[2*ks][1]);
                pa[1] = pack_h2(sc[2*ks][2],   sc[2*ks][3]);
                pa[2] = pack_h2(sc[2*ks+1][0], sc[2*ks+1][1]);
                pa[3] = pack_h2(sc[2*ks+1][2], sc[2*ks+1][3]);
#pragma unroll
                for (int np = 0; np < 4; np++) {
                    uint32_t vb[4];
                    ldsm_x4(vb, Vc + np * 16 * FROW + ks * 32);
                    mma_f16(oacc[2*np],   pa, vb[0], vb[2]);
                    mma_f16(oacc[2*np+1], pa, vb[1], vb[3]);
                }
            }
        }
    }

    // finalize: quad-reduce l, normalize, store context fp16
    lrow[0] += __shfl_xor_sync(0xffffffffu, lrow[0], 1);
    lrow[0] += __shfl_xor_sync(0xffffffffu, lrow[0], 2);
    lrow[1] += __shfl_xor_sync(0xffffffffu, lrow[1], 1);
    lrow[1] += __shfl_xor_sync(0xffffffffu, lrow[1], 2);
    const float inv0 = 1.f / lrow[0];
    const float inv1 = 1.f / lrow[1];

    __half* og = g_Ch + ((size_t)(b * SS + r0)) * EE + h * DD;
#pragma unroll
    for (int nt = 0; nt < 8; nt++) {
        __half2 v0 = __floats2half2_rn(oacc[nt][0] * inv0, oacc[nt][1] * inv0);
        __half2 v1 = __floats2half2_rn(oacc[nt][2] * inv1, oacc[nt][3] * inv1);
        *(__half2*)(og + nt * 8 + 2 * tig)                  = v0;
        *(__half2*)(og + (size_t)8 * EE + nt * 8 + 2 * tig) = v1;
    }
}

// ---------------------------------------------------------------------------
// Launch
// ---------------------------------------------------------------------------
extern "C" void kernel_launch(void* const* d_in, const int* in_sizes, int n_in,
                              void* d_out, int out_size)
{
    const float* x    = (const float*)d_in[0];
    // d_in[1] is the causal mask (triu, k=1) — applied analytically (j<=i).
    const float* wq_w = (const float*)d_in[2];
    const float* wq_b = (const float*)d_in[3];
    const float* wk_w = (const float*)d_in[4];
    const float* wk_b = (const float*)d_in[5];
    const float* wv_w = (const float*)d_in[6];
    const float* wv_b = (const float*)d_in[7];
    const float* wo_w = (const float*)d_in[8];
    const float* wo_b = (const float*)d_in[9];
    float* out = (float*)d_out;

    cudaFuncSetAttribute(gemm_qkv,
                         cudaFuncAttributeMaxDynamicSharedMemorySize, GSMEM);
    cudaFuncSetAttribute(gemm_single,
                         cudaFuncAttributeMaxDynamicSharedMemorySize, GSMEM);
    cudaFuncSetAttribute(flash_tc,
                         cudaFuncAttributeMaxDynamicSharedMemorySize, FSMEM);

    // convert x + weights to fp16
    prep_h<<<1024, 256>>>(x, wq_w, wk_w, wv_w, wo_w);

    // fused Q/K/V projections (Q pre-scaled by log2e/8, V transposed)
    gemm_qkv<<<dim3(12, MM / 128), 256, GSMEM>>>(wq_b, wk_b, wv_b);

    // causal GQA flash attention (64 q-rows per CTA, 4 CTAs/SM)
    flash_tc<<<dim3(SS / 64, HH, BB), 128, FSMEM>>>(out);

    // output projection (fp32 out)
    gemm_single<<<dim3(EE / 128, MM / 128), 256, GSMEM>>>(wo_b, out);
}

// round 14
// speedup vs baseline: 1.0668x; 1.0668x over previous
#include <cuda_runtime.h>
#include <cuda_fp16.h>
#include <cstdint>

// Problem constants
#define BB   2
#define SS   2048
#define EE   1024
#define HH   16
#define HKV  4
#define DD   64
#define KVE  (HKV * DD)   // 256
#define MM   (BB * SS)    // 4096

// Scratch (allocation-free rule: __device__ globals) — all fp16
__device__ __half g_Qh[(size_t)MM * EE];    // Q (pre-scaled by log2e/8)
__device__ __half g_Kh[(size_t)MM * KVE];   // K
__device__ __half g_Vth[(size_t)KVE * MM];  // V transposed [d][pos]
__device__ __half g_Ch[(size_t)MM * EE];    // context
__device__ __half g_xh[(size_t)MM * EE];    // x
__device__ __half g_wqh[(size_t)EE * EE];
__device__ __half g_wkh[(size_t)KVE * EE];
__device__ __half g_wvh[(size_t)KVE * EE];
__device__ __half g_woh[(size_t)EE * EE];

__device__ __forceinline__ void mma_f16(float* c, const uint32_t* a,
                                        uint32_t b0, uint32_t b1) {
    asm volatile(
        "mma.sync.aligned.m16n8k16.row.col.f32.f16.f16.f32 "
        "{%0,%1,%2,%3}, {%4,%5,%6,%7}, {%8,%9}, {%0,%1,%2,%3};"
        : "+f"(c[0]), "+f"(c[1]), "+f"(c[2]), "+f"(c[3])
        : "r"(a[0]), "r"(a[1]), "r"(a[2]), "r"(a[3]), "r"(b0), "r"(b1));
}
__device__ __forceinline__ void ldsm_x4(uint32_t* r, uint32_t addr) {
    asm volatile("ldmatrix.sync.aligned.m8n8.x4.shared.b16 {%0,%1,%2,%3}, [%4];"
                 : "=r"(r[0]), "=r"(r[1]), "=r"(r[2]), "=r"(r[3])
                 : "r"(addr));
}
__device__ __forceinline__ void cp16(uint32_t d, const void* s) {
    asm volatile("cp.async.cg.shared.global [%0], [%1], 16;"
                 :: "r"(d), "l"(s) : "memory");
}
__device__ __forceinline__ void cp_commit() {
    asm volatile("cp.async.commit_group;" ::: "memory");
}
__device__ __forceinline__ void cp_wait0() {
    asm volatile("cp.async.wait_group 0;" ::: "memory");
}
__device__ __forceinline__ void cp_wait1() {
    asm volatile("cp.async.wait_group 1;" ::: "memory");
}
__device__ __forceinline__ uint32_t cvta_s(const void* p) {
    return (uint32_t)__cvta_generic_to_shared(p);
}
__device__ __forceinline__ uint32_t pack_h2(float lo, float hi) {
    __half2 h = __floats2half2_rn(lo, hi);
    return *(uint32_t*)&h;
}
__device__ __forceinline__ float ex2f(float x) {
    float y;
    asm("ex2.approx.f32 %0, %1;" : "=f"(y) : "f"(x));
    return y;
}

// Q projection scale: 1/sqrt(64) * log2(e)  (softmax done in base-2)
#define QSCALE 0.1803368801111244f

// ===========================================================================
// Prep: convert x + all weights to fp16
// ===========================================================================
#define NX  (MM * EE)
#define NWQ (EE * EE)
#define NWK (KVE * EE)
#define NTOT (NX + NWQ + 2 * NWK + NWQ)

__global__ void __launch_bounds__(256)
prep_h(const float* __restrict__ x,
       const float* __restrict__ wq, const float* __restrict__ wk,
       const float* __restrict__ wv, const float* __restrict__ wo)
{
    const int nvec = NTOT / 8;
    for (int i = blockIdx.x * blockDim.x + threadIdx.x; i < nvec;
         i += gridDim.x * blockDim.x) {
        const int e = i * 8;
        const float* src;
        __half* dst;
        int off;
        if (e < NX)                    { src = x;  dst = g_xh;  off = e; }
        else if (e < NX + NWQ)         { src = wq; dst = g_wqh; off = e - NX; }
        else if (e < NX + NWQ + NWK)   { src = wk; dst = g_wkh; off = e - NX - NWQ; }
        else if (e < NX + NWQ + 2*NWK) { src = wv; dst = g_wvh; off = e - NX - NWQ - NWK; }
        else                           { src = wo; dst = g_woh; off = e - NX - NWQ - 2*NWK; }
        float4 v0 = *(const float4*)(src + off);
        float4 v1 = *(const float4*)(src + off + 4);
        __half2 h[4];
        h[0] = __floats2half2_rn(v0.x, v0.y);
        h[1] = __floats2half2_rn(v0.z, v0.w);
        h[2] = __floats2half2_rn(v1.x, v1.y);
        h[3] = __floats2half2_rn(v1.z, v1.w);
        *(uint4*)(dst + off) = *(uint4*)h;
    }
}

// ===========================================================================
// fp16 tensor-core GEMM core (m16n8k16): 128x128 CTA tile, 256 thr,
// 8 warps (2M x 4N), warp 64x32. BK=64 halves, 3-stage cp.async ring.
// OUT: 0 = fp32, 1 = fp16, 2 = fp16 transposed, 3 = fp16 * QSCALE (Q)
// (round-11 config, passing @ 227us)
// ===========================================================================
#define GBK   64
#define GROW  144
#define GBUFB (128 * GROW)
#define GSTG  3
#define GSMEM (2 * GSTG * GBUFB)       // 110592 bytes

template <int OUT>
__device__ __forceinline__ void gemm_core(
    const __half* __restrict__ A, const __half* __restrict__ W,
    const float* __restrict__ bias, void* __restrict__ Cv,
    int Nc, int row0)
{
    extern __shared__ char smraw[];
    const uint32_t sbase = cvta_s(smraw);

    const int tid = threadIdx.x;

    const int r   = tid >> 1;
    const int seg = (tid & 1) * 32;
    const __half* Ag = A + (size_t)(row0 + r) * EE + seg;
    const __half* Wg = W + (size_t)r * EE + seg;
    const uint32_t Asd = sbase + r * GROW + seg * 2;
    const uint32_t Bsd = sbase + GSTG * GBUFB + r * GROW + seg * 2;

    const int lane = tid & 31;
    const int wid  = tid >> 5;
    const int wm   = (wid & 1) * 64;
    const int wn   = (wid >> 1) * 32;
    const int g    = lane >> 2;
    const int tig  = lane & 3;

    const uint32_t aoff = (wm + (lane & 15)) * GROW + ((lane & 16) ? 16 : 0);
    const uint32_t boff = (wn + (lane & 15)) * GROW + ((lane & 16) ? 16 : 0);

    float acc[4][4][4];
#pragma unroll
    for (int mt = 0; mt < 4; mt++)
#pragma unroll
        for (int nt = 0; nt < 4; nt++)
#pragma unroll
            for (int i = 0; i < 4; i++) acc[mt][nt][i] = 0.f;

#pragma unroll
    for (int s = 0; s < 2; s++) {
#pragma unroll
        for (int i = 0; i < 4; i++) {
            cp16(Asd + s * GBUFB + i * 16, Ag + s * GBK + i * 8);
            cp16(Bsd + s * GBUFB + i * 16, Wg + s * GBK + i * 8);
        }
        cp_commit();
    }

    const int NI = EE / GBK;
    int bcur = 0, bpre = 2;
    for (int it = 0; it < NI; it++) {
        if (it + 1 < NI) cp_wait1(); else cp_wait0();
        __syncthreads();

        if (it + 2 < NI) {
            const __half* a = Ag + (it + 2) * GBK;
            const __half* w = Wg + (it + 2) * GBK;
            const uint32_t ad = Asd + bpre * GBUFB;
            const uint32_t bd = Bsd + bpre * GBUFB;
#pragma unroll
            for (int i = 0; i < 4; i++) {
                cp16(ad + i * 16, a + i * 8);
                cp16(bd + i * 16, w + i * 8);
            }
            cp_commit();
        }

        const uint32_t Ab = sbase + bcur * GBUFB + aoff;
        const uint32_t Bb = sbase + GSTG * GBUFB + bcur * GBUFB + boff;
#pragma unroll
        for (int ks = 0; ks < 4; ks++) {
            uint32_t a[4][4], b[2][4];
#pragma unroll
            for (int mt = 0; mt < 4; mt++)
                ldsm_x4(a[mt], Ab + mt * 16 * GROW + ks * 32);
#pragma unroll
            for (int np = 0; np < 2; np++)
                ldsm_x4(b[np], Bb + np * 16 * GROW + ks * 32);
#pragma unroll
            for (int mt = 0; mt < 4; mt++)
#pragma unroll
                for (int np = 0; np < 2; np++) {
                    mma_f16(acc[mt][2*np],   a[mt], b[np][0], b[np][2]);
                    mma_f16(acc[mt][2*np+1], a[mt], b[np][1], b[np][3]);
                }
        }

        bcur = (bcur + 1 == GSTG) ? 0 : bcur + 1;
        bpre = (bpre + 1 == GSTG) ? 0 : bpre + 1;
    }

#pragma unroll
    for (int mt = 0; mt < 4; mt++) {
        const int rowa = row0 + wm + mt * 16 + g;
#pragma unroll
        for (int nt = 0; nt < 4; nt++) {
            const int cola = wn + nt * 8 + 2 * tig;
            const float2 bv = *(const float2*)(bias + cola);
            float s0 = acc[mt][nt][0] + bv.x;
            float s1 = acc[mt][nt][1] + bv.y;
            float s2 = acc[mt][nt][2] + bv.x;
            float s3 = acc[mt][nt][3] + bv.y;
            if (OUT == 0) {
                float* C = (float*)Cv;
                *(float2*)(C + (size_t)rowa * Nc + cola)       = make_float2(s0, s1);
                *(float2*)(C + (size_t)(rowa + 8) * Nc + cola) = make_float2(s2, s3);
            } else if (OUT == 2) {
                __half* C = (__half*)Cv;
                C[(size_t)cola * MM + rowa]           = __float2half_rn(s0);
                C[(size_t)(cola + 1) * MM + rowa]     = __float2half_rn(s1);
                C[(size_t)cola * MM + rowa + 8]       = __float2half_rn(s2);
                C[(size_t)(cola + 1) * MM + rowa + 8] = __float2half_rn(s3);
            } else {
                const float sc = (OUT == 3) ? QSCALE : 1.f;
                __half* C = (__half*)Cv;
                __half2 v0 = __floats2half2_rn(s0 * sc, s1 * sc);
                __half2 v1 = __floats2half2_rn(s2 * sc, s3 * sc);
                *(__half2*)(C + (size_t)rowa * Nc + cola)       = v0;
                *(__half2*)(C + (size_t)(rowa + 8) * Nc + cola) = v1;
            }
        }
    }
}

__global__ void __launch_bounds__(256, 2)
gemm_qkv(const float* __restrict__ bq, const float* __restrict__ bk,
         const float* __restrict__ bv)
{
    const int bx   = blockIdx.x;
    const int row0 = blockIdx.y * 128;
    if (bx < 8) {
        const int c0 = bx * 128;
        gemm_core<3>(g_xh, g_wqh + (size_t)c0 * EE, bq + c0, g_Qh + c0, EE, row0);
    } else if (bx < 10) {
        const int c0 = (bx - 8) * 128;
        gemm_core<1>(g_xh, g_wkh + (size_t)c0 * EE, bk + c0, g_Kh + c0, KVE, row0);
    } else {
        const int c0 = (bx - 10) * 128;
        gemm_core<2>(g_xh, g_wvh + (size_t)c0 * EE, bv + c0,
                     g_Vth + (size_t)c0 * MM, KVE, row0);
    }
}

__global__ void __launch_bounds__(256, 2)
gemm_single(const float* __restrict__ bias, float* __restrict__ C)
{
    const int c0 = blockIdx.x * 128;
    gemm_core<0>(g_Ch, g_woh + (size_t)c0 * EE, bias + c0, C + c0, EE,
                 blockIdx.y * 128);
}

// ===========================================================================
// fp16 flash attention (round-11 structure, proven 227.7us):
// 128 q-rows per CTA, 256 thr (8 warps x 16 rows), 2 CTAs/SM.
// 64-wide KV tiles, 2-stage cp.async ring, one barrier per tile.
// Softmax in base-2 (Q pre-scaled by log2e/8, ex2.approx).
// ===========================================================================
#define FROW  144                     // row stride bytes (64 halves + pad)
#define FQB   (128 * FROW)            // 18432
#define FKB   (64 * FROW)             // 9216
#define FSMEM (FQB + 4 * FKB)         // 55296 bytes

__global__ void __launch_bounds__(256, 2)
flash_tc(float* __restrict__ dummy)
{
    extern __shared__ char smraw[];
    const uint32_t sbase = cvta_s(smraw);

    const int tid  = threadIdx.x;
    const int lane = tid & 31;
    const int wid  = tid >> 5;
    const int g    = lane >> 2;
    const int tig  = lane & 3;
    const int m0   = (gridDim.x - 1 - blockIdx.x) * 128;   // heavy-first
    const int h    = blockIdx.y;
    const int b    = blockIdx.z;
    const int kvh  = h >> 2;

    // K/V staging: 4 threads per row, 16 halves (32 B = 2 cp16) each
    const int sr  = tid >> 2;          // 0..63
    const int sck = (tid & 3) * 16;
    const __half* kgb = g_Kh + ((size_t)(b * SS + sr)) * KVE + kvh * DD + sck;
    const __half* vgb = g_Vth + ((size_t)(kvh * DD + sr)) * MM + b * SS + sck;
    const uint32_t kd0 = sbase + FQB + sr * FROW + sck * 2;
    const uint32_t vd0 = sbase + FQB + 2 * FKB + sr * FROW + sck * 2;

    // fragment lane offsets
    const uint32_t qoff  = (wid * 16 + (lane & 15)) * FROW + ((lane & 16) ? 16 : 0);
    const uint32_t kvoff = (lane & 15) * FROW + ((lane & 16) ? 16 : 0);

    // stage Q (pre-scaled fp16): 2 threads/row, 4 cp16 each
    {
        const int rq   = tid >> 1;
        const int segq = (tid & 1) * 32;
        const __half* qg = g_Qh + ((size_t)(b * SS + m0 + rq)) * EE + h * DD + segq;
        const uint32_t qd = sbase + rq * FROW + segq * 2;
#pragma unroll
        for (int i = 0; i < 4; i++) cp16(qd + i * 16, qg + i * 8);
    }
    // stage KV tile 0 into buffer 0
#pragma unroll
    for (int i = 0; i < 2; i++) {
        cp16(kd0 + i * 16, kgb + i * 8);
        cp16(vd0 + i * 16, vgb + i * 8);
    }
    cp_commit();
    cp_wait0();
    __syncthreads();

    // Q A-fragments (4 k16-steps over d=64)
    uint32_t qa[4][4];
#pragma unroll
    for (int ks = 0; ks < 4; ks++)
        ldsm_x4(qa[ks], sbase + qoff + ks * 32);

    float oacc[8][4];
#pragma unroll
    for (int nt = 0; nt < 8; nt++)
#pragma unroll
        for (int i = 0; i < 4; i++) oacc[nt][i] = 0.f;
    float mrow[2] = { -1e30f, -1e30f };
    float lrow[2] = { 0.f, 0.f };

    const int r0 = m0 + wid * 16 + g;
    const int ntile = m0 / 64 + 2;

    for (int t = 0; t < ntile; t++) {
        const int cb = t & 1;

        if (t > 0) {
            cp_wait0();
            __syncthreads();
        }

        if (t + 1 < ntile) {
            const __half* kg = kgb + (size_t)((t + 1) * 64) * KVE;
            const __half* vg = vgb + (t + 1) * 64;
            const uint32_t kd = kd0 + (1 - cb) * FKB;
            const uint32_t vd = vd0 + (1 - cb) * FKB;
#pragma unroll
            for (int i = 0; i < 2; i++) {
                cp16(kd + i * 16, kg + i * 8);
                cp16(vd + i * 16, vg + i * 8);
            }
            cp_commit();
        }

        const int j0 = t * 64;
        const bool active = (j0 <= m0 + wid * 16 + 15);    // warp-uniform
        if (active) {
            const uint32_t Kc = sbase + FQB + cb * FKB + kvoff;
            const uint32_t Vc = sbase + FQB + 2 * FKB + cb * FKB + kvoff;

            // S' = Q' @ K^T (log2 domain)
            float sc[8][4];
#pragma unroll
            for (int nt = 0; nt < 8; nt++)
#pragma unroll
                for (int i = 0; i < 4; i++) sc[nt][i] = 0.f;
#pragma unroll
            for (int ks = 0; ks < 4; ks++) {
#pragma unroll
                for (int np = 0; np < 4; np++) {
                    uint32_t kb[4];
                    ldsm_x4(kb, Kc + np * 16 * FROW + ks * 32);
                    mma_f16(sc[2*np],   qa[ks], kb[0], kb[2]);
                    mma_f16(sc[2*np+1], qa[ks], kb[1], kb[3]);
                }
            }

            // causal mask (diagonal tiles only)
            if (j0 + 63 > r0) {
#pragma unroll
                for (int nt = 0; nt < 8; nt++) {
                    const int c = j0 + nt * 8 + 2 * tig;
                    if (c     > r0)     sc[nt][0] = -1e30f;
                    if (c + 1 > r0)     sc[nt][1] = -1e30f;
                    if (c     > r0 + 8) sc[nt][2] = -1e30f;
                    if (c + 1 > r0 + 8) sc[nt][3] = -1e30f;
                }
            }

            // row max (quad reduce)
            float tm0 = -1e30f, tm1 = -1e30f;
#pragma unroll
            for (int nt = 0; nt < 8; nt++) {
                tm0 = fmaxf(tm0, fmaxf(sc[nt][0], sc[nt][1]));
                tm1 = fmaxf(tm1, fmaxf(sc[nt][2], sc[nt][3]));
            }
            tm0 = fmaxf(tm0, __shfl_xor_sync(0xffffffffu, tm0, 1));
            tm0 = fmaxf(tm0, __shfl_xor_sync(0xffffffffu, tm0, 2));
            tm1 = fmaxf(tm1, __shfl_xor_sync(0xffffffffu, tm1, 1));
            tm1 = fmaxf(tm1, __shfl_xor_sync(0xffffffffu, tm1, 2));

            const float mn0 = fmaxf(mrow[0], tm0);
            const float mn1 = fmaxf(mrow[1], tm1);
            const float cr0 = ex2f(mrow[0] - mn0);
            const float cr1 = ex2f(mrow[1] - mn1);
            mrow[0] = mn0; mrow[1] = mn1;

            float ls0 = 0.f, ls1 = 0.f;
#pragma unroll
            for (int nt = 0; nt < 8; nt++) {
                sc[nt][0] = ex2f(sc[nt][0] - mn0); ls0 += sc[nt][0];
                sc[nt][1] = ex2f(sc[nt][1] - mn0); ls0 += sc[nt][1];
                sc[nt][2] = ex2f(sc[nt][2] - mn1); ls1 += sc[nt][2];
                sc[nt][3] = ex2f(sc[nt][3] - mn1); ls1 += sc[nt][3];
            }
            lrow[0] = lrow[0] * cr0 + ls0;
            lrow[1] = lrow[1] * cr1 + ls1;
#pragma unroll
            for (int nt = 0; nt < 8; nt++) {
                oacc[nt][0] *= cr0; oacc[nt][1] *= cr0;
                oacc[nt][2] *= cr1; oacc[nt][3] *= cr1;
            }

            // O += P @ V — P converted in-register (C-frag == A-frag for f16)
#pragma unroll
            for (int ks = 0; ks < 4; ks++) {   // kv chunks of 16
                uint32_t pa[4];
                pa[0] = pack_h2(sc[2*ks][0],   sc[2*ks][1]);
                pa[1] = pack_h2(sc[2*ks][2],   sc[2*ks][3]);
                pa[2] = pack_h2(sc[2*ks+1][0], sc[2*ks+1][1]);
                pa[3] = pack_h2(sc[2*ks+1][2], sc[2*ks+1][3]);
#pragma unroll
                for (int np = 0; np < 4; np++) {
                    uint32_t vb[4];
                    ldsm_x4(vb, Vc + np * 16 * FROW + ks * 32);
                    mma_f16(oacc[2*np],   pa, vb[0], vb[2]);
                    mma_f16(oacc[2*np+1], pa, vb[1], vb[3]);
                }
            }
        }
    }

    // finalize: quad-reduce l, normalize, store context fp16
    lrow[0] += __shfl_xor_sync(0xffffffffu, lrow[0], 1);
    lrow[0] += __shfl_xor_sync(0xffffffffu, lrow[0], 2);
    lrow[1] += __shfl_xor_sync(0xffffffffu, lrow[1], 1);
    lrow[1] += __shfl_xor_sync(0xffffffffu, lrow[1], 2);
    const float inv0 = 1.f / lrow[0];
    const float inv1 = 1.f / lrow[1];

    __half* og = g_Ch + ((size_t)(b * SS + r0)) * EE + h * DD;
#pragma unroll
    for (int nt = 0; nt < 8; nt++) {
        __half2 v0 = __floats2half2_rn(oacc[nt][0] * inv0, oacc[nt][1] * inv0);
        __half2 v1 = __floats2half2_rn(oacc[nt][2] * inv1, oacc[nt][3] * inv1);
        *(__half2*)(og + nt * 8 + 2 * tig)                  = v0;
        *(__half2*)(og + (size_t)8 * EE + nt * 8 + 2 * tig) = v1;
    }
}

// ---------------------------------------------------------------------------
// Launch
// ---------------------------------------------------------------------------
extern "C" void kernel_launch(void* const* d_in, const int* in_sizes, int n_in,
                              void* d_out, int out_size)
{
    const float* x    = (const float*)d_in[0];
    // d_in[1] is the causal mask (triu, k=1) — applied analytically (j<=i).
    const float* wq_w = (const float*)d_in[2];
    const float* wq_b = (const float*)d_in[3];
    const float* wk_w = (const float*)d_in[4];
    const float* wk_b = (const float*)d_in[5];
    const float* wv_w = (const float*)d_in[6];
    const float* wv_b = (const float*)d_in[7];
    const float* wo_w = (const float*)d_in[8];
    const float* wo_b = (const float*)d_in[9];
    float* out = (float*)d_out;

    cudaFuncSetAttribute(gemm_qkv,
                         cudaFuncAttributeMaxDynamicSharedMemorySize, GSMEM);
    cudaFuncSetAttribute(gemm_single,
                         cudaFuncAttributeMaxDynamicSharedMemorySize, GSMEM);
    cudaFuncSetAttribute(flash_tc,
                         cudaFuncAttributeMaxDynamicSharedMemorySize, FSMEM);

    // convert x + weights to fp16
    prep_h<<<1024, 256>>>(x, wq_w, wk_w, wv_w, wo_w);

    // fused Q/K/V projections (Q pre-scaled by log2e/8, V transposed)
    gemm_qkv<<<dim3(12, MM / 128), 256, GSMEM>>>(wq_b, wk_b, wv_b);

    // causal GQA flash attention (round-11 structure + base-2 softmax)
    flash_tc<<<dim3(SS / 128, HH, BB), 256, FSMEM>>>(out);

    // output projection (fp32 out)
    gemm_single<<<dim3(EE / 128, MM / 128), 256, GSMEM>>>(wo_b, out);
}

// round 15
// speedup vs baseline: 1.0680x; 1.0011x over previous
#include <cuda_runtime.h>
#include <cuda_fp16.h>
#include <cstdint>

// Problem constants
#define BB   2
#define SS   2048
#define EE   1024
#define HH   16
#define HKV  4
#define DD   64
#define KVE  (HKV * DD)   // 256
#define MM   (BB * SS)    // 4096

// Scratch (allocation-free rule: __device__ globals) — all fp16
__device__ __half g_Qh[(size_t)MM * EE];    // Q (pre-scaled by log2e/8)
__device__ __half g_Kh[(size_t)MM * KVE];   // K
__device__ __half g_Vth[(size_t)KVE * MM];  // V transposed [d][pos]
__device__ __half g_Ch[(size_t)MM * EE];    // context
__device__ __half g_xh[(size_t)MM * EE];    // x
__device__ __half g_wqh[(size_t)EE * EE];
__device__ __half g_wkh[(size_t)KVE * EE];
__device__ __half g_wvh[(size_t)KVE * EE];
__device__ __half g_woh[(size_t)EE * EE];

__device__ __forceinline__ void mma_f16(float* c, const uint32_t* a,
                                        uint32_t b0, uint32_t b1) {
    asm volatile(
        "mma.sync.aligned.m16n8k16.row.col.f32.f16.f16.f32 "
        "{%0,%1,%2,%3}, {%4,%5,%6,%7}, {%8,%9}, {%0,%1,%2,%3};"
        : "+f"(c[0]), "+f"(c[1]), "+f"(c[2]), "+f"(c[3])
        : "r"(a[0]), "r"(a[1]), "r"(a[2]), "r"(a[3]), "r"(b0), "r"(b1));
}
__device__ __forceinline__ void ldsm_x4(uint32_t* r, uint32_t addr) {
    asm volatile("ldmatrix.sync.aligned.m8n8.x4.shared.b16 {%0,%1,%2,%3}, [%4];"
                 : "=r"(r[0]), "=r"(r[1]), "=r"(r[2]), "=r"(r[3])
                 : "r"(addr));
}
__device__ __forceinline__ void cp16(uint32_t d, const void* s) {
    asm volatile("cp.async.cg.shared.global [%0], [%1], 16;"
                 :: "r"(d), "l"(s) : "memory");
}
__device__ __forceinline__ void cp_commit() {
    asm volatile("cp.async.commit_group;" ::: "memory");
}
__device__ __forceinline__ void cp_wait0() {
    asm volatile("cp.async.wait_group 0;" ::: "memory");
}
__device__ __forceinline__ void cp_wait1() {
    asm volatile("cp.async.wait_group 1;" ::: "memory");
}
__device__ __forceinline__ uint32_t cvta_s(const void* p) {
    return (uint32_t)__cvta_generic_to_shared(p);
}
__device__ __forceinline__ uint32_t pack_h2(float lo, float hi) {
    __half2 h = __floats2half2_rn(lo, hi);
    return *(uint32_t*)&h;
}
__device__ __forceinline__ float ex2f(float x) {
    float y;
    asm("ex2.approx.f32 %0, %1;" : "=f"(y) : "f"(x));
    return y;
}

// Q projection scale: 1/sqrt(64) * log2(e)  (softmax done in base-2)
#define QSCALE 0.1803368801111244f

// ===========================================================================
// Prep: convert x + all weights to fp16
// ===========================================================================
#define NX  (MM * EE)
#define NWQ (EE * EE)
#define NWK (KVE * EE)
#define NTOT (NX + NWQ + 2 * NWK + NWQ)

__global__ void __launch_bounds__(256)
prep_h(const float* __restrict__ x,
       const float* __restrict__ wq, const float* __restrict__ wk,
       const float* __restrict__ wv, const float* __restrict__ wo)
{
    const int nvec = NTOT / 8;
    for (int i = blockIdx.x * blockDim.x + threadIdx.x; i < nvec;
         i += gridDim.x * blockDim.x) {
        const int e = i * 8;
        const float* src;
        __half* dst;
        int off;
        if (e < NX)                    { src = x;  dst = g_xh;  off = e; }
        else if (e < NX + NWQ)         { src = wq; dst = g_wqh; off = e - NX; }
        else if (e < NX + NWQ + NWK)   { src = wk; dst = g_wkh; off = e - NX - NWQ; }
        else if (e < NX + NWQ + 2*NWK) { src = wv; dst = g_wvh; off = e - NX - NWQ - NWK; }
        else                           { src = wo; dst = g_woh; off = e - NX - NWQ - 2*NWK; }
        float4 v0 = *(const float4*)(src + off);
        float4 v1 = *(const float4*)(src + off + 4);
        __half2 h[4];
        h[0] = __floats2half2_rn(v0.x, v0.y);
        h[1] = __floats2half2_rn(v0.z, v0.w);
        h[2] = __floats2half2_rn(v1.x, v1.y);
        h[3] = __floats2half2_rn(v1.z, v1.w);
        *(uint4*)(dst + off) = *(uint4*)h;
    }
}

// ===========================================================================
// fp16 tensor-core GEMM core (m16n8k16): 128x128 CTA tile, 256 thr,
// 8 warps (2M x 4N), warp 64x32. BK=64 halves, 3-stage cp.async ring.
// Fragment loads software-pipelined at mt granularity (a double-buffer).
// OUT: 0 = fp32, 1 = fp16, 2 = fp16 transposed, 3 = fp16 * QSCALE (Q)
// ===========================================================================
#define GBK   64
#define GROW  144
#define GBUFB (128 * GROW)
#define GSTG  3
#define GSMEM (2 * GSTG * GBUFB)       // 110592 bytes

template <int OUT>
__device__ __forceinline__ void gemm_core(
    const __half* __restrict__ A, const __half* __restrict__ W,
    const float* __restrict__ bias, void* __restrict__ Cv,
    int Nc, int row0)
{
    extern __shared__ char smraw[];
    const uint32_t sbase = cvta_s(smraw);

    const int tid = threadIdx.x;

    const int r   = tid >> 1;
    const int seg = (tid & 1) * 32;
    const __half* Ag = A + (size_t)(row0 + r) * EE + seg;
    const __half* Wg = W + (size_t)r * EE + seg;
    const uint32_t Asd = sbase + r * GROW + seg * 2;
    const uint32_t Bsd = sbase + GSTG * GBUFB + r * GROW + seg * 2;

    const int lane = tid & 31;
    const int wid  = tid >> 5;
    const int wm   = (wid & 1) * 64;
    const int wn   = (wid >> 1) * 32;
    const int g    = lane >> 2;
    const int tig  = lane & 3;

    const uint32_t aoff = (wm + (lane & 15)) * GROW + ((lane & 16) ? 16 : 0);
    const uint32_t boff = (wn + (lane & 15)) * GROW + ((lane & 16) ? 16 : 0);

    float acc[4][4][4];
#pragma unroll
    for (int mt = 0; mt < 4; mt++)
#pragma unroll
        for (int nt = 0; nt < 4; nt++)
#pragma unroll
            for (int i = 0; i < 4; i++) acc[mt][nt][i] = 0.f;

#pragma unroll
    for (int s = 0; s < 2; s++) {
#pragma unroll
        for (int i = 0; i < 4; i++) {
            cp16(Asd + s * GBUFB + i * 16, Ag + s * GBK + i * 8);
            cp16(Bsd + s * GBUFB + i * 16, Wg + s * GBK + i * 8);
        }
        cp_commit();
    }

    const int NI = EE / GBK;
    int bcur = 0, bpre = 2;
    for (int it = 0; it < NI; it++) {
        if (it + 1 < NI) cp_wait1(); else cp_wait0();
        __syncthreads();

        if (it + 2 < NI) {
            const __half* a = Ag + (it + 2) * GBK;
            const __half* w = Wg + (it + 2) * GBK;
            const uint32_t ad = Asd + bpre * GBUFB;
            const uint32_t bd = Bsd + bpre * GBUFB;
#pragma unroll
            for (int i = 0; i < 4; i++) {
                cp16(ad + i * 16, a + i * 8);
                cp16(bd + i * 16, w + i * 8);
            }
            cp_commit();
        }

        const uint32_t Ab = sbase + bcur * GBUFB + aoff;
        const uint32_t Bb = sbase + GSTG * GBUFB + bcur * GBUFB + boff;
#pragma unroll
        for (int ks = 0; ks < 4; ks++) {
            uint32_t b[2][4];
            ldsm_x4(b[0], Bb + 0 * 16 * GROW + ks * 32);
            ldsm_x4(b[1], Bb + 1 * 16 * GROW + ks * 32);
            uint32_t a[2][4];
            ldsm_x4(a[0], Ab + ks * 32);
#pragma unroll
            for (int mt = 0; mt < 4; mt++) {
                if (mt < 3)
                    ldsm_x4(a[(mt + 1) & 1], Ab + (mt + 1) * 16 * GROW + ks * 32);
                const uint32_t* am = a[mt & 1];
#pragma unroll
                for (int np = 0; np < 2; np++) {
                    mma_f16(acc[mt][2*np],   am, b[np][0], b[np][2]);
                    mma_f16(acc[mt][2*np+1], am, b[np][1], b[np][3]);
                }
            }
        }

        bcur = (bcur + 1 == GSTG) ? 0 : bcur + 1;
        bpre = (bpre + 1 == GSTG) ? 0 : bpre + 1;
    }

#pragma unroll
    for (int mt = 0; mt < 4; mt++) {
        const int rowa = row0 + wm + mt * 16 + g;
#pragma unroll
        for (int nt = 0; nt < 4; nt++) {
            const int cola = wn + nt * 8 + 2 * tig;
            const float2 bv = *(const float2*)(bias + cola);
            float s0 = acc[mt][nt][0] + bv.x;
            float s1 = acc[mt][nt][1] + bv.y;
            float s2 = acc[mt][nt][2] + bv.x;
            float s3 = acc[mt][nt][3] + bv.y;
            if (OUT == 0) {
                float* C = (float*)Cv;
                *(float2*)(C + (size_t)rowa * Nc + cola)       = make_float2(s0, s1);
                *(float2*)(C + (size_t)(rowa + 8) * Nc + cola) = make_float2(s2, s3);
            } else if (OUT == 2) {
                __half* C = (__half*)Cv;
                C[(size_t)cola * MM + rowa]           = __float2half_rn(s0);
                C[(size_t)(cola + 1) * MM + rowa]     = __float2half_rn(s1);
                C[(size_t)cola * MM + rowa + 8]       = __float2half_rn(s2);
                C[(size_t)(cola + 1) * MM + rowa + 8] = __float2half_rn(s3);
            } else {
                const float sc = (OUT == 3) ? QSCALE : 1.f;
                __half* C = (__half*)Cv;
                __half2 v0 = __floats2half2_rn(s0 * sc, s1 * sc);
                __half2 v1 = __floats2half2_rn(s2 * sc, s3 * sc);
                *(__half2*)(C + (size_t)rowa * Nc + cola)       = v0;
                *(__half2*)(C + (size_t)(rowa + 8) * Nc + cola) = v1;
            }
        }
    }
}

__global__ void __launch_bounds__(256, 2)
gemm_qkv(const float* __restrict__ bq, const float* __restrict__ bk,
         const float* __restrict__ bv)
{
    const int bx   = blockIdx.x;
    const int row0 = blockIdx.y * 128;
    if (bx < 8) {
        const int c0 = bx * 128;
        gemm_core<3>(g_xh, g_wqh + (size_t)c0 * EE, bq + c0, g_Qh + c0, EE, row0);
    } else if (bx < 10) {
        const int c0 = (bx - 8) * 128;
        gemm_core<1>(g_xh, g_wkh + (size_t)c0 * EE, bk + c0, g_Kh + c0, KVE, row0);
    } else {
        const int c0 = (bx - 10) * 128;
        gemm_core<2>(g_xh, g_wvh + (size_t)c0 * EE, bv + c0,
                     g_Vth + (size_t)c0 * MM, KVE, row0);
    }
}

__global__ void __launch_bounds__(256, 2)
gemm_single(const float* __restrict__ bias, float* __restrict__ C)
{
    const int c0 = blockIdx.x * 128;
    gemm_core<0>(g_Ch, g_woh + (size_t)c0 * EE, bias + c0, C + c0, EE,
                 blockIdx.y * 128);
}

// ===========================================================================
// fp16 flash attention (round-11 structure, base-2 softmax):
// 128 q-rows per CTA, 256 thr (8 warps x 16 rows), 2 CTAs/SM.
// 64-wide KV tiles, 2-stage cp.async ring, one barrier per tile.
// K/V fragment loads software-pipelined at np granularity.
// ===========================================================================
#define FROW  144                     // row stride bytes (64 halves + pad)
#define FQB   (128 * FROW)            // 18432
#define FKB   (64 * FROW)             // 9216
#define FSMEM (FQB + 4 * FKB)         // 55296 bytes

__global__ void __launch_bounds__(256, 2)
flash_tc(float* __restrict__ dummy)
{
    extern __shared__ char smraw[];
    const uint32_t sbase = cvta_s(smraw);

    const int tid  = threadIdx.x;
    const int lane = tid & 31;
    const int wid  = tid >> 5;
    const int g    = lane >> 2;
    const int tig  = lane & 3;
    const int m0   = (gridDim.x - 1 - blockIdx.x) * 128;   // heavy-first
    const int h    = blockIdx.y;
    const int b    = blockIdx.z;
    const int kvh  = h >> 2;

    // K/V staging: 4 threads per row, 16 halves (32 B = 2 cp16) each
    const int sr  = tid >> 2;          // 0..63
    const int sck = (tid & 3) * 16;
    const __half* kgb = g_Kh + ((size_t)(b * SS + sr)) * KVE + kvh * DD + sck;
    const __half* vgb = g_Vth + ((size_t)(kvh * DD + sr)) * MM + b * SS + sck;
    const uint32_t kd0 = sbase + FQB + sr * FROW + sck * 2;
    const uint32_t vd0 = sbase + FQB + 2 * FKB + sr * FROW + sck * 2;

    // fragment lane offsets
    const uint32_t qoff  = (wid * 16 + (lane & 15)) * FROW + ((lane & 16) ? 16 : 0);
    const uint32_t kvoff = (lane & 15) * FROW + ((lane & 16) ? 16 : 0);

    // stage Q (pre-scaled fp16): 2 threads/row, 4 cp16 each
    {
        const int rq   = tid >> 1;
        const int segq = (tid & 1) * 32;
        const __half* qg = g_Qh + ((size_t)(b * SS + m0 + rq)) * EE + h * DD + segq;
        const uint32_t qd = sbase + rq * FROW + segq * 2;
#pragma unroll
        for (int i = 0; i < 4; i++) cp16(qd + i * 16, qg + i * 8);
    }
    // stage KV tile 0 into buffer 0
#pragma unroll
    for (int i = 0; i < 2; i++) {
        cp16(kd0 + i * 16, kgb + i * 8);
        cp16(vd0 + i * 16, vgb + i * 8);
    }
    cp_commit();
    cp_wait0();
    __syncthreads();

    // Q A-fragments (4 k16-steps over d=64)
    uint32_t qa[4][4];
#pragma unroll
    for (int ks = 0; ks < 4; ks++)
        ldsm_x4(qa[ks], sbase + qoff + ks * 32);

    float oacc[8][4];
#pragma unroll
    for (int nt = 0; nt < 8; nt++)
#pragma unroll
        for (int i = 0; i < 4; i++) oacc[nt][i] = 0.f;
    float mrow[2] = { -1e30f, -1e30f };
    float lrow[2] = { 0.f, 0.f };

    const int r0 = m0 + wid * 16 + g;
    const int ntile = m0 / 64 + 2;

    for (int t = 0; t < ntile; t++) {
        const int cb = t & 1;

        if (t > 0) {
            cp_wait0();
            __syncthreads();
        }

        if (t + 1 < ntile) {
            const __half* kg = kgb + (size_t)((t + 1) * 64) * KVE;
            const __half* vg = vgb + (t + 1) * 64;
            const uint32_t kd = kd0 + (1 - cb) * FKB;
            const uint32_t vd = vd0 + (1 - cb) * FKB;
#pragma unroll
            for (int i = 0; i < 2; i++) {
                cp16(kd + i * 16, kg + i * 8);
                cp16(vd + i * 16, vg + i * 8);
            }
            cp_commit();
        }

        const int j0 = t * 64;
        const bool active = (j0 <= m0 + wid * 16 + 15);    // warp-uniform
        if (active) {
            const uint32_t Kc = sbase + FQB + cb * FKB + kvoff;
            const uint32_t Vc = sbase + FQB + 2 * FKB + cb * FKB + kvoff;

            // S' = Q' @ K^T (log2 domain), kb pipelined across np
            float sc[8][4];
#pragma unroll
            for (int nt = 0; nt < 8; nt++)
#pragma unroll
                for (int i = 0; i < 4; i++) sc[nt][i] = 0.f;
#pragma unroll
            for (int ks = 0; ks < 4; ks++) {
                uint32_t kb[2][4];
                ldsm_x4(kb[0], Kc + ks * 32);
#pragma unroll
                for (int np = 0; np < 4; np++) {
                    if (np < 3)
                        ldsm_x4(kb[(np + 1) & 1],
                                Kc + (np + 1) * 16 * FROW + ks * 32);
                    const uint32_t* kp = kb[np & 1];
                    mma_f16(sc[2*np],   qa[ks], kp[0], kp[2]);
                    mma_f16(sc[2*np+1], qa[ks], kp[1], kp[3]);
                }
            }

            // causal mask (diagonal tiles only)
            if (j0 + 63 > r0) {
#pragma unroll
                for (int nt = 0; nt < 8; nt++) {
                    const int c = j0 + nt * 8 + 2 * tig;
                    if (c     > r0)     sc[nt][0] = -1e30f;
                    if (c + 1 > r0)     sc[nt][1] = -1e30f;
                    if (c     > r0 + 8) sc[nt][2] = -1e30f;
                    if (c + 1 > r0 + 8) sc[nt][3] = -1e30f;
                }
            }

            // row max (quad reduce)
            float tm0 = -1e30f, tm1 = -1e30f;
#pragma unroll
            for (int nt = 0; nt < 8; nt++) {
                tm0 = fmaxf(tm0, fmaxf(sc[nt][0], sc[nt][1]));
                tm1 = fmaxf(tm1, fmaxf(sc[nt][2], sc[nt][3]));
            }
            tm0 = fmaxf(tm0, __shfl_xor_sync(0xffffffffu, tm0, 1));
            tm0 = fmaxf(tm0, __shfl_xor_sync(0xffffffffu, tm0, 2));
            tm1 = fmaxf(tm1, __shfl_xor_sync(0xffffffffu, tm1, 1));
            tm1 = fmaxf(tm1, __shfl_xor_sync(0xffffffffu, tm1, 2));

            const float mn0 = fmaxf(mrow[0], tm0);
            const float mn1 = fmaxf(mrow[1], tm1);
            const float cr0 = ex2f(mrow[0] - mn0);
            const float cr1 = ex2f(mrow[1] - mn1);
            mrow[0] = mn0; mrow[1] = mn1;

            float ls0 = 0.f, ls1 = 0.f;
#pragma unroll
            for (int nt = 0; nt < 8; nt++) {
                sc[nt][0] = ex2f(sc[nt][0] - mn0); ls0 += sc[nt][0];
                sc[nt][1] = ex2f(sc[nt][1] - mn0); ls0 += sc[nt][1];
                sc[nt][2] = ex2f(sc[nt][2] - mn1); ls1 += sc[nt][2];
                sc[nt][3] = ex2f(sc[nt][3] - mn1); ls1 += sc[nt][3];
            }
            lrow[0] = lrow[0] * cr0 + ls0;
            lrow[1] = lrow[1] * cr1 + ls1;
#pragma unroll
            for (int nt = 0; nt < 8; nt++) {
                oacc[nt][0] *= cr0; oacc[nt][1] *= cr0;
                oacc[nt][2] *= cr1; oacc[nt][3] *= cr1;
            }

            // O += P @ V — P in registers, vb pipelined across np
#pragma unroll
            for (int ks = 0; ks < 4; ks++) {   // kv chunks of 16
                uint32_t pa[4];
                pa[0] = pack_h2(sc[2*ks][0],   sc[2*ks][1]);
                pa[1] = pack_h2(sc[2*ks][2],   sc[2*ks][3]);
                pa[2] = pack_h2(sc[2*ks+1][0], sc[2*ks+1][1]);
                pa[3] = pack_h2(sc[2*ks+1][2], sc[2*ks+1][3]);
                uint32_t vb[2][4];
                ldsm_x4(vb[0], Vc + ks * 32);
#pragma unroll
                for (int np = 0; np < 4; np++) {
                    if (np < 3)
                        ldsm_x4(vb[(np + 1) & 1],
                                Vc + (np + 1) * 16 * FROW + ks * 32);
                    const uint32_t* vp = vb[np & 1];
                    mma_f16(oacc[2*np],   pa, vp[0], vp[2]);
                    mma_f16(oacc[2*np+1], pa, vp[1], vp[3]);
                }
            }
        }
    }

    // finalize: quad-reduce l, normalize, store context fp16
    lrow[0] += __shfl_xor_sync(0xffffffffu, lrow[0], 1);
    lrow[0] += __shfl_xor_sync(0xffffffffu, lrow[0], 2);
    lrow[1] += __shfl_xor_sync(0xffffffffu, lrow[1], 1);
    lrow[1] += __shfl_xor_sync(0xffffffffu, lrow[1], 2);
    const float inv0 = 1.f / lrow[0];
    const float inv1 = 1.f / lrow[1];

    __half* og = g_Ch + ((size_t)(b * SS + r0)) * EE + h * DD;
#pragma unroll
    for (int nt = 0; nt < 8; nt++) {
        __half2 v0 = __floats2half2_rn(oacc[nt][0] * inv0, oacc[nt][1] * inv0);
        __half2 v1 = __floats2half2_rn(oacc[nt][2] * inv1, oacc[nt][3] * inv1);
        *(__half2*)(og + nt * 8 + 2 * tig)                  = v0;
        *(__half2*)(og + (size_t)8 * EE + nt * 8 + 2 * tig) = v1;
    }
}

// ---------------------------------------------------------------------------
// Launch
// ---------------------------------------------------------------------------
extern "C" void kernel_launch(void* const* d_in, const int* in_sizes, int n_in,
                              void* d_out, int out_size)
{
    const float* x    = (const float*)d_in[0];
    // d_in[1] is the causal mask (triu, k=1) — applied analytically (j<=i).
    const float* wq_w = (const float*)d_in[2];
    const float* wq_b = (const float*)d_in[3];
    const float* wk_w = (const float*)d_in[4];
    const float* wk_b = (const float*)d_in[5];
    const float* wv_w = (const float*)d_in[6];
    const float* wv_b = (const float*)d_in[7];
    const float* wo_w = (const float*)d_in[8];
    const float* wo_b = (const float*)d_in[9];
    float* out = (float*)d_out;

    cudaFuncSetAttribute(gemm_qkv,
                         cudaFuncAttributeMaxDynamicSharedMemorySize, GSMEM);
    cudaFuncSetAttribute(gemm_single,
                         cudaFuncAttributeMaxDynamicSharedMemorySize, GSMEM);
    cudaFuncSetAttribute(flash_tc,
                         cudaFuncAttributeMaxDynamicSharedMemorySize, FSMEM);

    // convert x + weights to fp16
    prep_h<<<1024, 256>>>(x, wq_w, wk_w, wv_w, wo_w);

    // fused Q/K/V projections (Q pre-scaled by log2e/8, V transposed)
    gemm_qkv<<<dim3(12, MM / 128), 256, GSMEM>>>(wq_b, wk_b, wv_b);

    // causal GQA flash attention
    flash_tc<<<dim3(SS / 128, HH, BB), 256, FSMEM>>>(out);

    // output projection (fp32 out)
    gemm_single<<<dim3(EE / 128, MM / 128), 256, GSMEM>>>(wo_b, out);
}